// round 14
// baseline (speedup 1.0000x reference)
#include <cuda_runtime.h>
#include <cuda_bf16.h>
#include <cstdint>

#define B_    128
#define T_    512
#define D_    256
#define H_    1024
#define G4_   4096
#define Z_    128
#define NBLK  128
#define NTHR  256        // 8 warps; warp w owns rows [16w,16w+16)
#define XROW  512        // g_xi row elems (8 chunks * 64)
#define HROW  2048       // g_hx row elems (32 chunks * 64)

// dynamic smem map (bytes)
#define SM_B      1024                 // 80 ktiles * 2048 B (fragment-order) = 160 KB
#define SM_A      164864               // 8 warps * 4 slots * 2048 B = 64 KB (warp-private rings)
#define SM_SIZE   230400

#define SWZ(o) ((o) ^ ((((o) >> 3) & 0x70)))

// ---------------- persistent device state ----------------
__device__ __align__(16) __nv_bfloat16 g_Ub[(size_t)NBLK * 81920];     // frag-order B
__device__ __align__(16) __nv_bfloat16 g_xi[(size_t)B_ * T_ * XROW];   // x hi/lo
__device__ __align__(16) __nv_bfloat16 g_hx[2][(size_t)B_ * HROW];     // h hi/lo
__device__ float         g_h32[(size_t)B_ * H_];
__device__ unsigned int  g_bar;

// ---------------- helpers ----------------
__device__ __forceinline__ uint32_t smem_u32(const void* p) {
    uint32_t a;
    asm("{ .reg .u64 t; cvta.to.shared.u64 t, %1; cvt.u32.u64 %0, t; }" : "=r"(a) : "l"(p));
    return a;
}
__device__ __forceinline__ void cp_async16(uint32_t dst, const void* src) {
    asm volatile("cp.async.cg.shared.global [%0], [%1], 16;" :: "r"(dst), "l"(src) : "memory");
}
__device__ __forceinline__ void ldsm4(uint32_t* r, uint32_t addr) {
    asm volatile("ldmatrix.sync.aligned.m8n8.x4.shared.b16 {%0,%1,%2,%3}, [%4];"
                 : "=r"(r[0]), "=r"(r[1]), "=r"(r[2]), "=r"(r[3]) : "r"(addr));
}
__device__ __forceinline__ void mma_bf16(float* d, const uint32_t* a, uint32_t b0, uint32_t b1) {
    asm volatile(
        "mma.sync.aligned.m16n8k16.row.col.f32.bf16.bf16.f32 "
        "{%0,%1,%2,%3}, {%4,%5,%6,%7}, {%8,%9}, {%0,%1,%2,%3};"
        : "+f"(d[0]), "+f"(d[1]), "+f"(d[2]), "+f"(d[3])
        : "r"(a[0]), "r"(a[1]), "r"(a[2]), "r"(a[3]), "r"(b0), "r"(b1));
}
__device__ __forceinline__ void st_cg_u32(void* p, uint32_t v) {
    asm volatile("st.global.cg.u32 [%0], %1;" :: "l"(p), "r"(v) : "memory");
}
__device__ __forceinline__ float sigmoid_f(float x) { return 1.0f / (1.0f + expf(-x)); }
__device__ __forceinline__ float softplus_f(float x) {
    return fmaxf(x, 0.0f) + log1pf(expf(-fabsf(x)));
}

// ---------------- prep kernels ----------------
__global__ void reset_kernel() {
    int i = blockIdx.x * blockDim.x + threadIdx.x;
    if (i == 0) g_bar = 0u;
    uint4* p = (uint4*)&g_hx[0][0];
    for (int e = i; e < (int)((size_t)B_ * HROW * 2 / 16); e += gridDim.x * blockDim.x)
        p[e] = make_uint4(0, 0, 0, 0);
}

// x[B,T,D] fp32 -> g_xi: per row, 8 chunks of [16hi|16lo|16hi|16lo] (64 elems)
__global__ void xprep_kernel(const float* __restrict__ x) {
    size_t e = (size_t)blockIdx.x * blockDim.x + threadIdx.x;   // < B*T*D
    float v = x[e];
    __nv_bfloat16 hi = __float2bfloat16(v);
    __nv_bfloat16 lo = __float2bfloat16(v - __bfloat162float(hi));
    size_t bt = e >> 8;
    int k = (int)(e & 255);
    int c = k >> 5, sub = (k >> 4) & 1, pos = k & 15;
    __nv_bfloat16* d = g_xi + bt * XROW + c * 64 + sub * 32 + pos;
    d[0] = hi; d[16] = lo;
}

// W[256,4096], U[1024,4096] -> per-block fragment-order B images.
__global__ void uprep_kernel(const float* __restrict__ W, const float* __restrict__ U) {
    size_t id = (size_t)blockIdx.x * blockDim.x + threadIdx.x;   // < 128*40960
    int bid = (int)(id / 40960);
    int r   = (int)(id % 40960);
    int kt   = r >> 9;
    int r2   = r & 511;
    int half = r2 >> 8;
    int lane = (r2 >> 3) & 31;
    int e    = r2 & 7;
    int nip = e >> 2, rg = (e >> 1) & 1, i = e & 1;
    int k = kt * 16 + (lane & 3) * 2 + rg * 8 + i;
    int n = (half * 2 + nip) * 8 + (lane >> 2);
    int gcol = (n >> 3) * H_ + bid * 8 + (n & 7);
    float v = (k < 256) ? W[(size_t)k * G4_ + gcol]
                        : U[(size_t)(k - 256) * G4_ + gcol];
    __nv_bfloat16 hi = __float2bfloat16(v);
    __nv_bfloat16 lo = __float2bfloat16(v - __bfloat162float(hi));
    __nv_bfloat16* base = g_Ub + (size_t)bid * 81920 +
                          (size_t)((kt * 2 + half) * 2) * 256 + lane * 8 + e;
    base[0]   = hi;     // hl=0
    base[256] = lo;     // hl=1
}

// ---------------- main persistent kernel ----------------
__global__ void __launch_bounds__(NTHR, 1)
lstm_kernel(const float* __restrict__ bias)
{
    extern __shared__ char smem[];
    const uint32_t sb = smem_u32(smem);
    const int tid  = threadIdx.x;
    const int w    = tid >> 5;          // 0..7, owns rows [16w, 16w+16)
    const int lane = tid & 31;
    const int bid  = blockIdx.x;
    const int j0   = bid * 8;
    const uint32_t wbase = sb + SM_A + w * 8192;   // warp-private 4-slot ring

    // Load resident fragment-order B (160 KB) once.
    {
        const char* src = (const char*)(g_Ub + (size_t)bid * 81920);
        for (int i = tid; i < 10240; i += NTHR)
            cp_async16(sb + SM_B + i * 16, src + (size_t)i * 16);
        asm volatile("cp.async.commit_group;\n\tcp.async.wait_group 0;" ::: "memory");
    }
    __syncthreads();

    // ---- hoisted per-thread address constants ----
    const int row16 = lane & 15;                 // staging row within warp tile
    const int hh    = (lane >> 4) * 64;          // staging half (0 / 64B)
    uint32_t dsw[4];                             // swizzled dst offsets in slot
#pragma unroll
    for (int q = 0; q < 4; q++)
        dsw[q] = SWZ((uint32_t)(row16 * 128 + hh + q * 16));
    const char* px_base = (const char*)(g_xi + (size_t)(w * 16 + row16) * T_ * XROW) + hh;
    const char* ph_base[2] = {
        (const char*)(g_hx[0] + (size_t)(w * 16 + row16) * HROW) + hh,
        (const char*)(g_hx[1] + (size_t)(w * 16 + row16) * HROW) + hh };

    const int lm_row = (lane & 7) + ((lane >> 3) & 1) * 8;
    const int lm_k   = (lane >> 4) & 1;
    uint32_t lsw[4];                             // ldmatrix offsets: sub0 hi/lo, sub1 hi/lo
    lsw[0] = SWZ((uint32_t)(lm_row * 128 + lm_k * 16));
    lsw[1] = SWZ((uint32_t)(lm_row * 128 + lm_k * 16 + 32));
    lsw[2] = SWZ((uint32_t)(lm_row * 128 + 64 + lm_k * 16));
    lsw[3] = SWZ((uint32_t)(lm_row * 128 + 64 + lm_k * 16 + 32));
    const char* bB = smem + SM_B + lane * 16;    // B fragments base for this lane

    float bR[4][2];
#pragma unroll
    for (int g = 0; g < 4; g++)
#pragma unroll
        for (int p = 0; p < 2; p++)
            bR[g][p] = bias[g * H_ + j0 + (lane & 3) * 2 + p];

    float creg[4];
#pragma unroll
    for (int i = 0; i < 4; i++) creg[i] = 0.f;

    // prologue: x-chunks 0..2 of t=0 into slots 0..2
#pragma unroll
    for (int p = 0; p < 3; p++) {
        uint32_t slot = wbase + p * 2048;
        const char* src = px_base + p * 128;          // t=0
#pragma unroll
        for (int q = 0; q < 4; q++) cp_async16(slot + dsw[q], src + q * 16);
        asm volatile("cp.async.commit_group;" ::: "memory");
    }

    for (int t = 0; t < T_; t++) {
        const char* px_t = px_base + t * 1024;        // x row for step t
        const char* ph_t = ph_base[t & 1];
        const char* pxn  = px_t + 1024;               // next step's x row

        float acc[4][4];
#pragma unroll
        for (int nt = 0; nt < 4; nt++)
#pragma unroll
            for (int i = 0; i < 4; i++) acc[nt][i] = 0.f;

        for (int g = 0; g < 40; g++) {
            // late-wait: first h chunk (ig=8) is issued at g==5
            if (g == 5 && t > 0) {
                const unsigned target = (unsigned)t * (unsigned)NBLK;
                while (*(volatile unsigned*)&g_bar < target) { __nanosleep(32); }
                __threadfence();
            }

            // issue chunk g+3 into slot (g+3)&3 (old occupant consumed last iter)
            const int ig = g + 3;
            if (ig < 40 || t + 1 < T_) {
                const char* src = (ig < 8)  ? px_t + ig * 128
                                : (ig < 40) ? ph_t + (ig - 8) * 128
                                            : pxn + (ig - 40) * 128;   // next-step x prefetch
                uint32_t slot = wbase + (ig & 3) * 2048;
#pragma unroll
                for (int q = 0; q < 4; q++) cp_async16(slot + dsw[q], src + q * 16);
                asm volatile("cp.async.commit_group;" ::: "memory");
            } else {
                asm volatile("cp.async.commit_group;" ::: "memory");
            }

            // chunk g arrived when at most 3 newer groups pending
            asm volatile("cp.async.wait_group 3;" ::: "memory");
            __syncwarp();

            const uint32_t stA = wbase + (g & 3) * 2048;
            const char* bbc = bB + g * 4096;          // kt = 2g
#pragma unroll
            for (int sub = 0; sub < 2; sub++) {
                uint32_t ah[4], al[4];
                ldsm4(ah, stA + lsw[sub * 2 + 0]);
                ldsm4(al, stA + lsw[sub * 2 + 1]);
                const char* bb = bbc + sub * 2048;
                uint4 h0 = *(const uint4*)(bb);            // hi, ntiles 0,1
                uint4 l0 = *(const uint4*)(bb + 512);      // lo, ntiles 0,1
                uint4 h1 = *(const uint4*)(bb + 1024);     // hi, ntiles 2,3
                uint4 l1 = *(const uint4*)(bb + 1536);     // lo, ntiles 2,3
                uint32_t bh[4][2] = {{h0.x, h0.y}, {h0.z, h0.w}, {h1.x, h1.y}, {h1.z, h1.w}};
                uint32_t bl[4][2] = {{l0.x, l0.y}, {l0.z, l0.w}, {l1.x, l1.y}, {l1.z, l1.w}};
#pragma unroll
                for (int nt = 0; nt < 4; nt++) {
                    mma_bf16(acc[nt], ah, bh[nt][0], bh[nt][1]);
                    mma_bf16(acc[nt], al, bh[nt][0], bh[nt][1]);
                    mma_bf16(acc[nt], ah, bl[nt][0], bl[nt][1]);
                }
            }
        }

        // ---- epilogue: cell update, fully lane-local (16 rows per warp) ----
        {
            char* hwB = (char*)(g_hx[(t + 1) & 1]);
            const int cbyte = (j0 >> 5) * 128 + ((j0 >> 4) & 1) * 64 +
                              ((j0 & 15) + (lane & 3) * 2) * 2;
#pragma unroll
            for (int rs = 0; rs < 2; rs++) {
                const int row = w * 16 + (lane >> 2) + rs * 8;
                __nv_bfloat16 hhi[2], hlo[2];
#pragma unroll
                for (int p = 0; p < 2; p++) {
                    const int ai = rs * 2 + p;
                    float gi = acc[0][ai] + bR[0][p];
                    float gf = acc[1][ai] + bR[1][p];
                    float gg = acc[2][ai] + bR[2][p];
                    float go = acc[3][ai] + bR[3][p];
                    float iv = sigmoid_f(gi), fv = sigmoid_f(gf), ov = sigmoid_f(go);
                    float gv = softplus_f(gg);
                    const int ci = rs * 2 + p;
                    float cn = fv * creg[ci] + iv * gv;
                    creg[ci] = cn;
                    float hn = ov * softplus_f(cn);
                    hhi[p] = __float2bfloat16(hn);
                    hlo[p] = __float2bfloat16(hn - __bfloat162float(hhi[p]));
                    if (t == T_ - 1)
                        g_h32[(size_t)row * H_ + j0 + (lane & 3) * 2 + p] = hn;
                }
                char* base = hwB + (size_t)row * 4096 + cbyte;
                uint32_t phi = (uint32_t)__bfloat16_as_ushort(hhi[0]) |
                               ((uint32_t)__bfloat16_as_ushort(hhi[1]) << 16);
                uint32_t plo = (uint32_t)__bfloat16_as_ushort(hlo[0]) |
                               ((uint32_t)__bfloat16_as_ushort(hlo[1]) << 16);
                st_cg_u32(base,      phi);
                st_cg_u32(base + 32, plo);
            }
        }

        // ---- early arrive: release our h writes; wait happens next step @ g==5 ----
        __syncthreads();
        if (tid == 0) {
            __threadfence();
            atomicAdd(&g_bar, 1u);
        }
    }
}

// ---------------- final projections (fp32) ----------------
__global__ void __launch_bounds__(Z_)
proj_kernel(const float* __restrict__ Wm, const float* __restrict__ bm,
            const float* __restrict__ Wv, const float* __restrict__ bv,
            const float* __restrict__ eps, float* __restrict__ out)
{
    __shared__ float hs[H_];
    const int b = blockIdx.x;
    const int z = threadIdx.x;
    const float* hrow = g_h32 + (size_t)b * H_;
    for (int k = z; k < H_; k += Z_) hs[k] = hrow[k];
    __syncthreads();

    float am = bm[z];
    float av = bv[z];
#pragma unroll 4
    for (int k = 0; k < H_; k++) {
        float hk = hs[k];
        am += hk * Wm[(size_t)k * Z_ + z];
        av += hk * Wv[(size_t)k * Z_ + z];
    }
    float zz = am + eps[(size_t)b * Z_ + z] * expf(0.5f * av);
    out[(size_t)b * Z_ + z]                 = am;
    out[(size_t)(B_ * Z_) + b * Z_ + z]     = av;
    out[(size_t)(2 * B_ * Z_) + b * Z_ + z] = zz;
}

// ---------------------------------------------------------------------------
extern "C" void kernel_launch(void* const* d_in, const int* in_sizes, int n_in,
                              void* d_out, int out_size)
{
    const float* x   = (const float*)d_in[0];
    const float* W   = (const float*)d_in[1];
    const float* U   = (const float*)d_in[2];
    const float* b   = (const float*)d_in[3];
    const float* Wm  = (const float*)d_in[4];
    const float* bm  = (const float*)d_in[5];
    const float* Wv  = (const float*)d_in[6];
    const float* bv  = (const float*)d_in[7];
    const float* eps = (const float*)d_in[8];
    float* out = (float*)d_out;

    cudaFuncSetAttribute(lstm_kernel, cudaFuncAttributeMaxDynamicSharedMemorySize, SM_SIZE);

    reset_kernel<<<256, 256>>>();
    xprep_kernel<<<(B_ * T_ * D_) / 256, 256>>>(x);
    uprep_kernel<<<(NBLK * 40960) / 256, 256>>>(W, U);
    lstm_kernel<<<NBLK, NTHR, SM_SIZE>>>(b);
    proj_kernel<<<B_, Z_>>>(Wm, bm, Wv, bv, eps, out);
}

// round 15
// speedup vs baseline: 1.3016x; 1.3016x over previous
#include <cuda_runtime.h>
#include <cuda_bf16.h>
#include <cstdint>

#define B_    128
#define T_    512
#define D_    256
#define H_    1024
#define G4_   4096
#define Z_    128
#define NBLK  128
#define NTHR  256        // 8 warps; warp w owns rows [16w,16w+16)

// dynamic smem map (bytes): B only
#define SM_B      1024                 // 80 ktiles * 2048 B (fragment-order) = 160 KB
#define SM_SIZE   165888

// ---------------- persistent device state ----------------
// A fragment-order blocks: [chunk][mtile(8)] x 2048 B, inner (sub2,hl2,lane32,e4 words)
__device__ __align__(16) __nv_bfloat16 g_Ub[(size_t)NBLK * 81920];     // frag-order B
__device__ __align__(16) char g_xf[(size_t)T_ * 8 * 8 * 2048];         // x frags (64 MB)
__device__ __align__(16) char g_hf[2][32 * 8 * 2048];                  // h frags (512 KB x2)
__device__ float         g_h32[(size_t)B_ * H_];
__device__ unsigned int  g_bar;

// ---------------- helpers ----------------
__device__ __forceinline__ uint32_t smem_u32(const void* p) {
    uint32_t a;
    asm("{ .reg .u64 t; cvta.to.shared.u64 t, %1; cvt.u32.u64 %0, t; }" : "=r"(a) : "l"(p));
    return a;
}
__device__ __forceinline__ void cp_async16(uint32_t dst, const void* src) {
    asm volatile("cp.async.cg.shared.global [%0], [%1], 16;" :: "r"(dst), "l"(src) : "memory");
}
__device__ __forceinline__ void mma_bf16(float* d, const uint32_t* a, uint32_t b0, uint32_t b1) {
    asm volatile(
        "mma.sync.aligned.m16n8k16.row.col.f32.bf16.bf16.f32 "
        "{%0,%1,%2,%3}, {%4,%5,%6,%7}, {%8,%9}, {%0,%1,%2,%3};"
        : "+f"(d[0]), "+f"(d[1]), "+f"(d[2]), "+f"(d[3])
        : "r"(a[0]), "r"(a[1]), "r"(a[2]), "r"(a[3]), "r"(b0), "r"(b1));
}
__device__ __forceinline__ void st_cg_u32(void* p, uint32_t v) {
    asm volatile("st.global.cg.u32 [%0], %1;" :: "l"(p), "r"(v) : "memory");
}
__device__ __forceinline__ float sigmoid_f(float x) { return 1.0f / (1.0f + expf(-x)); }
__device__ __forceinline__ float softplus_f(float x) {
    return fmaxf(x, 0.0f) + log1pf(expf(-fabsf(x)));
}

// ---------------- prep kernels ----------------
__global__ void reset_kernel() {
    int i = blockIdx.x * blockDim.x + threadIdx.x;
    if (i == 0) g_bar = 0u;
    uint4* p = (uint4*)&g_hf[0][0];
    for (int e = i; e < (int)(sizeof(g_hf[0]) / 16); e += gridDim.x * blockDim.x)
        p[e] = make_uint4(0, 0, 0, 0);
}

// x[B,T,D] fp32 -> g_xf fragment order
__global__ void xprep_kernel(const float* __restrict__ x) {
    size_t e = (size_t)blockIdx.x * blockDim.x + threadIdx.x;   // < B*T*D
    float v = x[e];
    __nv_bfloat16 hi = __float2bfloat16(v);
    __nv_bfloat16 lo = __float2bfloat16(v - __bfloat162float(hi));
    int b = (int)(e / ((size_t)T_ * D_));
    int r = (int)(e % ((size_t)T_ * D_));
    int t = r / D_, d = r % D_;
    int m = b >> 4, rl = b & 15;
    int c = d >> 5, kk = d & 31, sub = kk >> 4, k16 = kk & 15;
    int lane = (rl & 7) * 4 + ((k16 & 7) >> 1);
    int ee   = (rl >> 3) + 2 * (k16 >> 3);
    int i    = k16 & 1;
    size_t off = (((size_t)(t * 8 + c) * 8 + m) * 2048) + sub * 1024 + lane * 16 + ee * 4 + i * 2;
    *(__nv_bfloat16*)(g_xf + off)       = hi;   // hl=0
    *(__nv_bfloat16*)(g_xf + off + 512) = lo;   // hl=1
}

// W[256,4096], U[1024,4096] -> per-block fragment-order B images (validated R10).
__global__ void uprep_kernel(const float* __restrict__ W, const float* __restrict__ U) {
    size_t id = (size_t)blockIdx.x * blockDim.x + threadIdx.x;   // < 128*40960
    int bid = (int)(id / 40960);
    int r   = (int)(id % 40960);
    int kt   = r >> 9;
    int r2   = r & 511;
    int half = r2 >> 8;
    int lane = (r2 >> 3) & 31;
    int e    = r2 & 7;
    int nip = e >> 2, rg = (e >> 1) & 1, i = e & 1;
    int k = kt * 16 + (lane & 3) * 2 + rg * 8 + i;
    int n = (half * 2 + nip) * 8 + (lane >> 2);
    int gcol = (n >> 3) * H_ + bid * 8 + (n & 7);
    float v = (k < 256) ? W[(size_t)k * G4_ + gcol]
                        : U[(size_t)(k - 256) * G4_ + gcol];
    __nv_bfloat16 hi = __float2bfloat16(v);
    __nv_bfloat16 lo = __float2bfloat16(v - __bfloat162float(hi));
    __nv_bfloat16* base = g_Ub + (size_t)bid * 81920 +
                          (size_t)((kt * 2 + half) * 2) * 256 + lane * 8 + e;
    base[0]   = hi;
    base[256] = lo;
}

// ---------------- chunk macros ----------------
#define LOADX(S, P) do {                                  \
    sl[S][0] = __ldg((const uint4*)(P));                  \
    sl[S][1] = __ldg((const uint4*)((P) + 512));          \
    sl[S][2] = __ldg((const uint4*)((P) + 1024));         \
    sl[S][3] = __ldg((const uint4*)((P) + 1536));         \
} while (0)
#define LOADH(S, P) do {                                  \
    sl[S][0] = __ldcg((const uint4*)(P));                 \
    sl[S][1] = __ldcg((const uint4*)((P) + 512));         \
    sl[S][2] = __ldcg((const uint4*)((P) + 1024));        \
    sl[S][3] = __ldcg((const uint4*)((P) + 1536));        \
} while (0)
#define CHUNK(S, BPTR) do {                                                   \
    _Pragma("unroll")                                                         \
    for (int sub = 0; sub < 2; sub++) {                                       \
        const char* bb = (BPTR) + sub * 2048;                                 \
        uint4 h0 = *(const uint4*)(bb);                                       \
        uint4 l0 = *(const uint4*)(bb + 512);                                 \
        uint4 h1 = *(const uint4*)(bb + 1024);                                \
        uint4 l1 = *(const uint4*)(bb + 1536);                                \
        const uint32_t* ah = (const uint32_t*)&sl[S][sub * 2];                \
        const uint32_t* al = (const uint32_t*)&sl[S][sub * 2 + 1];            \
        uint32_t bh[4][2] = {{h0.x,h0.y},{h0.z,h0.w},{h1.x,h1.y},{h1.z,h1.w}};\
        uint32_t bl[4][2] = {{l0.x,l0.y},{l0.z,l0.w},{l1.x,l1.y},{l1.z,l1.w}};\
        _Pragma("unroll")                                                     \
        for (int nt = 0; nt < 4; nt++) {                                      \
            mma_bf16(acc[nt], ah, bh[nt][0], bh[nt][1]);                      \
            mma_bf16(acc[nt], al, bh[nt][0], bh[nt][1]);                      \
            mma_bf16(acc[nt], ah, bl[nt][0], bl[nt][1]);                      \
        }                                                                     \
    }                                                                         \
} while (0)

// ---------------- main persistent kernel ----------------
__global__ void __launch_bounds__(NTHR, 1)
lstm_kernel(const float* __restrict__ bias)
{
    extern __shared__ char smem[];
    const uint32_t sb = smem_u32(smem);
    const int tid  = threadIdx.x;
    const int w    = tid >> 5;          // 0..7, owns rows [16w, 16w+16)
    const int lane = tid & 31;
    const int bid  = blockIdx.x;
    const int j0   = bid * 8;

    // Load resident fragment-order B (160 KB) once.
    {
        const char* src = (const char*)(g_Ub + (size_t)bid * 81920);
        for (int i = tid; i < 10240; i += NTHR)
            cp_async16(sb + SM_B + i * 16, src + (size_t)i * 16);
        asm volatile("cp.async.commit_group;\n\tcp.async.wait_group 0;" ::: "memory");
    }
    __syncthreads();

    // hoisted per-thread pointers
    const char* pxB  = g_xf    + w * 2048 + lane * 16;
    const char* phB0 = g_hf[0] + w * 2048 + lane * 16;
    const char* phB1 = g_hf[1] + w * 2048 + lane * 16;
    const char* bB   = smem + SM_B + lane * 16;

    float bR[4][2];
#pragma unroll
    for (int g = 0; g < 4; g++)
#pragma unroll
        for (int p = 0; p < 2; p++)
            bR[g][p] = bias[g * H_ + j0 + (lane & 3) * 2 + p];

    float creg[4];
#pragma unroll
    for (int i = 0; i < 4; i++) creg[i] = 0.f;

    uint4 sl[4][4];
    // prologue: x-chunks 0..3 of t=0
#pragma unroll
    for (int s = 0; s < 4; s++) LOADX(s, pxB + s * 16384);

    for (int t = 0; t < T_; t++) {
        const char* px = pxB + (size_t)t * 131072;
        const char* ph = (t & 1) ? phB1 : phB0;

        float acc[4][4];
#pragma unroll
        for (int nt = 0; nt < 4; nt++)
#pragma unroll
            for (int i = 0; i < 4; i++) acc[nt][i] = 0.f;

        // ---- phase A: chunks 0..3 (x); load x-chunks 4..7 ----
        CHUNK(0, bB);          LOADX(0, px + 4 * 16384);
        CHUNK(1, bB + 4096);   LOADX(1, px + 5 * 16384);
        CHUNK(2, bB + 8192);   LOADX(2, px + 6 * 16384);
        CHUNK(3, bB + 12288);  LOADX(3, px + 7 * 16384);

        // barrier wait before first h-load issue
        if (t) {
            const unsigned target = (unsigned)t * (unsigned)NBLK;
            while (*(volatile unsigned*)&g_bar < target) { __nanosleep(32); }
            __threadfence();
        }

        // ---- phase B: chunks 4..35; load h-chunks 0..31 ----
        {
            const char* bp = bB + 4 * 4096;
            const char* hp = ph;
#pragma unroll 1
            for (int gg = 0; gg < 8; gg++) {
                CHUNK(0, bp);          LOADH(0, hp);
                CHUNK(1, bp + 4096);   LOADH(1, hp + 16384);
                CHUNK(2, bp + 8192);   LOADH(2, hp + 32768);
                CHUNK(3, bp + 12288);  LOADH(3, hp + 49152);
                bp += 16384; hp += 65536;
            }
            // ---- phase C: chunks 36..39; prefetch next step's x-chunks 0..3 ----
            if (t + 1 < T_) {
                const char* pxn = px + 131072;
                CHUNK(0, bp);          LOADX(0, pxn);
                CHUNK(1, bp + 4096);   LOADX(1, pxn + 16384);
                CHUNK(2, bp + 8192);   LOADX(2, pxn + 32768);
                CHUNK(3, bp + 12288);  LOADX(3, pxn + 49152);
            } else {
                CHUNK(0, bp); CHUNK(1, bp + 4096);
                CHUNK(2, bp + 8192); CHUNK(3, bp + 12288);
            }
        }

        // ---- epilogue: cell update; write h frags for consumers ----
        {
            // writer target: c=bid>>2, m=w, sub=(bid>>1)&1, lane'=lane, e=rs+2*(bid&1)
            char* wh = g_hf[(t + 1) & 1] +
                       ((size_t)(bid >> 2) * 8 + w) * 2048 +
                       ((bid >> 1) & 1) * 1024 + lane * 16 + (bid & 1) * 8;
#pragma unroll
            for (int rs = 0; rs < 2; rs++) {
                const int row = w * 16 + (lane >> 2) + rs * 8;
                __nv_bfloat16 hhi[2], hlo[2];
#pragma unroll
                for (int p = 0; p < 2; p++) {
                    const int ai = rs * 2 + p;
                    float gi = acc[0][ai] + bR[0][p];
                    float gf = acc[1][ai] + bR[1][p];
                    float gg = acc[2][ai] + bR[2][p];
                    float go = acc[3][ai] + bR[3][p];
                    float iv = sigmoid_f(gi), fv = sigmoid_f(gf), ov = sigmoid_f(go);
                    float gv = softplus_f(gg);
                    const int ci = rs * 2 + p;
                    float cn = fv * creg[ci] + iv * gv;
                    creg[ci] = cn;
                    float hn = ov * softplus_f(cn);
                    hhi[p] = __float2bfloat16(hn);
                    hlo[p] = __float2bfloat16(hn - __bfloat162float(hhi[p]));
                    if (t == T_ - 1)
                        g_h32[(size_t)row * H_ + j0 + (lane & 3) * 2 + p] = hn;
                }
                uint32_t phi = (uint32_t)__bfloat16_as_ushort(hhi[0]) |
                               ((uint32_t)__bfloat16_as_ushort(hhi[1]) << 16);
                uint32_t plo = (uint32_t)__bfloat16_as_ushort(hlo[0]) |
                               ((uint32_t)__bfloat16_as_ushort(hlo[1]) << 16);
                st_cg_u32(wh + rs * 4,       phi);   // hl=0
                st_cg_u32(wh + 512 + rs * 4, plo);   // hl=1
            }
        }

        // ---- early arrive; wait happens next step before h loads ----
        __syncthreads();
        if (tid == 0) {
            __threadfence();
            atomicAdd(&g_bar, 1u);
        }
    }
}

// ---------------- final projections (fp32) ----------------
__global__ void __launch_bounds__(Z_)
proj_kernel(const float* __restrict__ Wm, const float* __restrict__ bm,
            const float* __restrict__ Wv, const float* __restrict__ bv,
            const float* __restrict__ eps, float* __restrict__ out)
{
    __shared__ float hs[H_];
    const int b = blockIdx.x;
    const int z = threadIdx.x;
    const float* hrow = g_h32 + (size_t)b * H_;
    for (int k = z; k < H_; k += Z_) hs[k] = hrow[k];
    __syncthreads();

    float am = bm[z];
    float av = bv[z];
#pragma unroll 4
    for (int k = 0; k < H_; k++) {
        float hk = hs[k];
        am += hk * Wm[(size_t)k * Z_ + z];
        av += hk * Wv[(size_t)k * Z_ + z];
    }
    float zz = am + eps[(size_t)b * Z_ + z] * expf(0.5f * av);
    out[(size_t)b * Z_ + z]                 = am;
    out[(size_t)(B_ * Z_) + b * Z_ + z]     = av;
    out[(size_t)(2 * B_ * Z_) + b * Z_ + z] = zz;
}

// ---------------------------------------------------------------------------
extern "C" void kernel_launch(void* const* d_in, const int* in_sizes, int n_in,
                              void* d_out, int out_size)
{
    const float* x   = (const float*)d_in[0];
    const float* W   = (const float*)d_in[1];
    const float* U   = (const float*)d_in[2];
    const float* b   = (const float*)d_in[3];
    const float* Wm  = (const float*)d_in[4];
    const float* bm  = (const float*)d_in[5];
    const float* Wv  = (const float*)d_in[6];
    const float* bv  = (const float*)d_in[7];
    const float* eps = (const float*)d_in[8];
    float* out = (float*)d_out;

    cudaFuncSetAttribute(lstm_kernel, cudaFuncAttributeMaxDynamicSharedMemorySize, SM_SIZE);

    reset_kernel<<<256, 256>>>();
    xprep_kernel<<<(B_ * T_ * D_) / 256, 256>>>(x);
    uprep_kernel<<<(NBLK * 40960) / 256, 256>>>(W, U);
    lstm_kernel<<<NBLK, NTHR, SM_SIZE>>>(b);
    proj_kernel<<<B_, Z_>>>(Wm, bm, Wv, bv, eps, out);
}